// round 14
// baseline (speedup 1.0000x reference)
#include <cuda_runtime.h>
#include <cuda_fp16.h>

// Problem shape (fixed by the dataset): N=50000, E=800000, Fn=128, Fe=64, D=64
#define MAXN 50176
#define MAXE 800000
#define DD   64
#define FN   128
#define FE   64
#define SLOPE 0.05f
#define FULL 0xffffffffu

// ---------------- scratch (device globals; no allocation) ----------------
__device__ __half2 d_h16[MAXN * 32];         // h fp16 [N,64]   (6.4 MB)
__device__ __half2 d_eah[(size_t)MAXE * 32]; // edge_attr fp16  (102 MB)
__device__ float  d_hi[MAXN], d_hj[MAXN], d_he[MAXN];
__device__ float4 d_u4[16];             // u[64] = W_edge^T @ a_edge[D:]
__device__ float  d_ge[MAXE];           // per-edge score part: edge_attr[k].u
__device__ int    d_ei32[2 * MAXE];     // edge indices as int32
__device__ int    d_srcn[MAXE];         // CSR(node): source j per slot
__device__ int    d_srce[2 * MAXE];     // CSR(edge): edge id per slot
__device__ int    d_deg_n[MAXN], d_deg_e[MAXN];
__device__ int    d_off_n[MAXN + 1], d_off_e[MAXN + 1];
__device__ int    d_cur_n[MAXN], d_cur_e[MAXN];
__device__ int    d_not64;

__device__ __forceinline__ float leaky(float v) { return v >= 0.f ? v : SLOPE * v; }

// ---------------- K1: zero degree counters + dtype detect -------------------
__global__ void k_init(const void* __restrict__ ei, int twoE, int N) {
    int i = blockIdx.x * blockDim.x + threadIdx.x;
    if (i < N) { d_deg_n[i] = 0; d_deg_e[i] = 0; }
    if (i == 0) d_not64 = 0;
    // detect: if data is int64, every value must be in [0,N). Only the first
    // twoE/2 int64 words are guaranteed in-bounds if the buffer is int32.
    if (i < twoE / 2) {
        long long v = ((const long long*)ei)[i];
        if (v < 0 || v >= N) atomicExch(&d_not64, 1);
    }
}

// ---------------- K2: convert indices + histogram degrees -------------------
__global__ void k_convert_hist(const void* __restrict__ ei, int twoE, int E) {
    int i = blockIdx.x * blockDim.x + threadIdx.x;
    if (i >= twoE) return;
    int v;
    if (d_not64) v = ((const int*)ei)[i];
    else         v = (int)((const long long*)ei)[i];
    d_ei32[i] = v;
    if (i < E) atomicAdd(&d_deg_n[v], 1);   // node branch: targets only
    atomicAdd(&d_deg_e[v], 1);              // edge branch: both endpoints
}

// ---------------- K3: single-block scan of both degree arrays ---------------
__global__ void k_scan_all(int N, int E) {
    __shared__ int sn[1024], se[1024];
    int t = threadIdx.x;
    int carry_n = 0, carry_e = 0;
    for (int base = 0; base < N; base += 1024) {
        int i = base + t;
        int vn = (i < N) ? d_deg_n[i] : 0;
        int ve = (i < N) ? d_deg_e[i] : 0;
        sn[t] = vn; se[t] = ve;
        __syncthreads();
        for (int o = 1; o < 1024; o <<= 1) {
            int a = (t >= o) ? sn[t - o] : 0;
            int b = (t >= o) ? se[t - o] : 0;
            __syncthreads();
            sn[t] += a; se[t] += b;
            __syncthreads();
        }
        if (i < N) {
            int en = carry_n + sn[t] - vn;
            int ee = carry_e + se[t] - ve;
            d_off_n[i] = en; d_cur_n[i] = en;
            d_off_e[i] = ee; d_cur_e[i] = ee;
        }
        carry_n += sn[1023];
        carry_e += se[1023];
        __syncthreads();
    }
    if (t == 0) { d_off_n[N] = E; d_off_e[N] = 2 * E; }
}

// ---------------- K4 (PROFILED): scatter permutation ------------------------
__global__ void k_scatter(int E) {
    int k = blockIdx.x * blockDim.x + threadIdx.x;
    if (k >= E) return;
    int i = d_ei32[k], j = d_ei32[E + k];
    int pn = atomicAdd(&d_cur_n[i], 1);
    d_srcn[pn] = j;
    int p1 = atomicAdd(&d_cur_e[i], 1);
    d_srce[p1] = k;
    int p2 = atomicAdd(&d_cur_e[j], 1);
    d_srce[p2] = k;
}

// ---------------- K5: u[f] = sum_d a_edge[D+d] * W_edge[d][f] ---------------
__global__ void k_u(const float* __restrict__ We, const float* __restrict__ a_edge) {
    int f = threadIdx.x;  // 64 threads
    float acc = 0.f;
    #pragma unroll 8
    for (int dd = 0; dd < DD; dd++) acc = fmaf(a_edge[DD + dd], We[dd * FE + f], acc);
    ((float*)d_u4)[f] = acc;
}

// ---------------- K6: ge[k] = edge_attr[k].u + fp16 staging -----------------
__global__ void k_ge(const float* __restrict__ ea, int E) {
    int tid = blockIdx.x * blockDim.x + threadIdx.x;
    int k = tid >> 4;
    int l = tid & 15;
    bool valid = (k < E);
    int kk = valid ? k : 0;
    const float4* ea4 = (const float4*)ea;
    float4 v = ea4[(size_t)kk * 16 + l];
    if (valid) {
        d_eah[(size_t)k * 32 + 2 * l]     = __floats2half2_rn(v.x, v.y);
        d_eah[(size_t)k * 32 + 2 * l + 1] = __floats2half2_rn(v.z, v.w);
    }
    float4 u = d_u4[l];
    float p = v.x * u.x + v.y * u.y + v.z * u.z + v.w * u.w;
    #pragma unroll
    for (int o = 8; o; o >>= 1) p += __shfl_xor_sync(FULL, p, o, 16);
    if (valid && l == 0) d_ge[k] = p;
}

// ---------------- K7: h = x @ W_node^T (+ attention dots + fp16 store) ------
__global__ void k_h(const float* __restrict__ x, const float* __restrict__ Wn,
                    const float* __restrict__ an, const float* __restrict__ ae, int N) {
    __shared__ float4 Wsh[64 * 32];   // 32 KB, swizzled
    __shared__ float4 xsh[32 * 32];   // 16 KB
    __shared__ float  hsh[32 * 65];   // 8.3 KB, h tile (padded)
    int t = threadIdx.x;
    const float4* Wn4 = (const float4*)Wn;
    for (int idx = t; idx < 64 * 32; idx += 256) {
        int d = idx >> 5, c4 = idx & 31;
        Wsh[d * 32 + ((c4 + d) & 31)] = Wn4[idx];
    }
    int nb = blockIdx.x * 32;
    const float4* x4 = (const float4*)x;
    for (int idx = t; idx < 32 * 32; idx += 256) {
        int nl = idx >> 5, c4 = idx & 31;
        int n = nb + nl;
        xsh[idx] = (n < N) ? x4[(size_t)n * 32 + c4] : make_float4(0.f, 0.f, 0.f, 0.f);
    }
    __syncthreads();

    int d0 = t & 15, g = t >> 4;
    float acc[2][4] = {};
    #pragma unroll 4
    for (int f4 = 0; f4 < 32; f4++) {
        float4 w[4];
        #pragma unroll
        for (int k = 0; k < 4; k++) {
            int d = d0 + 16 * k;
            w[k] = Wsh[d * 32 + ((f4 + d) & 31)];
        }
        float4 xa = xsh[(g * 2 + 0) * 32 + f4];
        float4 xb = xsh[(g * 2 + 1) * 32 + f4];
        #pragma unroll
        for (int k = 0; k < 4; k++) {
            acc[0][k] = fmaf(xa.x, w[k].x, fmaf(xa.y, w[k].y, fmaf(xa.z, w[k].z, fmaf(xa.w, w[k].w, acc[0][k]))));
            acc[1][k] = fmaf(xb.x, w[k].x, fmaf(xb.y, w[k].y, fmaf(xb.z, w[k].z, fmaf(xb.w, w[k].w, acc[1][k]))));
        }
    }
    #pragma unroll
    for (int s = 0; s < 2; s++) {
        int nl = g * 2 + s;
        #pragma unroll
        for (int k = 0; k < 4; k++)
            hsh[nl * 65 + d0 + 16 * k] = acc[s][k];
    }
    __syncthreads();

    for (int idx = t; idx < 32 * 32; idx += 256) {
        int nl = idx >> 5, c = idx & 31;
        int n = nb + nl;
        if (n < N)
            d_h16[(size_t)n * 32 + c] =
                __floats2half2_rn(hsh[nl * 65 + 2 * c], hsh[nl * 65 + 2 * c + 1]);
    }

    int warp = t >> 5, lane = t & 31;
    for (int q = 0; q < 4; q++) {
        int nl = warp * 4 + q;
        int n = nb + nl;
        float v0 = hsh[nl * 65 + lane];
        float v1 = hsh[nl * 65 + 32 + lane];
        float p1 = v0 * an[lane]      + v1 * an[lane + 32];
        float p2 = v0 * an[64 + lane] + v1 * an[96 + lane];
        float p3 = v0 * ae[lane]      + v1 * ae[lane + 32];
        #pragma unroll
        for (int o = 16; o; o >>= 1) {
            p1 += __shfl_xor_sync(FULL, p1, o);
            p2 += __shfl_xor_sync(FULL, p2, o);
            p3 += __shfl_xor_sync(FULL, p3, o);
        }
        if (lane == 0 && n < N) { d_hi[n] = p1; d_hj[n] = p2; d_he[n] = p3; }
    }
}

// ---------------- K8: fused accumulate + project (chunk-cooperative) --------
// Per 32-slot chunk: ONE coalesced index load, ONE gathered score load,
// ONE warp-wide exp — then shfl-broadcast while gathering payload rows.
// Cuts L1tex wavefronts/iteration ~3x and MUFU work 32x vs R12.
__global__ void k_acc(const float* __restrict__ We, float* __restrict__ out, int N) {
    __shared__ float Wsh[64 * 65];   // W_edge padded (16.6 KB)
    __shared__ float tesh[8][64];    // per-warp te stage
    int t = threadIdx.x;
    for (int idx = t; idx < 64 * 64; idx += 256)
        Wsh[(idx >> 6) * 65 + (idx & 63)] = We[idx];
    __syncthreads();   // last block-wide sync — safe for early warp returns below

    int warp = t >> 5, lane = t & 31;
    int n = blockIdx.x * 8 + warp;
    if (n >= N) return;

    // ---- node branch ----
    {
        int off = d_off_n[n], end = d_off_n[n + 1];
        float hi_n = d_hi[n];
        float2 acc = make_float2(0.f, 0.f);
        float s = 0.f;   // all lanes hold the same sum (broadcast values)
        for (int base = off; base < end; base += 32) {
            int m = end - base;                 // slots in this chunk
            int p = base + lane;
            int jv = (lane < m) ? d_srcn[p] : 0;
            float sc = 0.f;
            if (lane < m) sc = __expf(leaky(hi_n + d_hj[jv]));
            int iter = m < 32 ? m : 32;
            #pragma unroll 4
            for (int q = 0; q < iter; q++) {
                int   j  = __shfl_sync(FULL, jv, q);
                float ex = __shfl_sync(FULL, sc, q);
                float2 f = __half22float2(d_h16[(size_t)j * 32 + lane]);
                acc.x = fmaf(ex, f.x, acc.x);
                acc.y = fmaf(ex, f.y, acc.y);
                s += ex;
            }
        }
        float exs = __expf(leaky(hi_n + d_hj[n]));   // self loop
        s += exs;
        float inv = 1.f / (s * (float)(end - off + 1));
        float2 hv = __half22float2(d_h16[(size_t)n * 32 + lane]);
        float2 r;
        r.x = leaky(fmaf(exs, hv.x, acc.x) * inv);
        r.y = leaky(fmaf(exs, hv.y, acc.y) * inv);
        ((float2*)out)[(size_t)n * 64 + lane] = r;   // out[n, 0:64]
    }

    // ---- edge branch ----
    {
        int off = d_off_e[n], end = d_off_e[n + 1];
        int ce = end - off;
        float he_n = d_he[n];
        float2 te = make_float2(0.f, 0.f);
        float s = 0.f;
        for (int base = off; base < end; base += 32) {
            int m = end - base;
            int p = base + lane;
            int kv = (lane < m) ? d_srce[p] : 0;
            float sc = 0.f;
            if (lane < m) sc = __expf(leaky(he_n + d_ge[kv]));
            int iter = m < 32 ? m : 32;
            #pragma unroll 4
            for (int q = 0; q < iter; q++) {
                int   k  = __shfl_sync(FULL, kv, q);
                float ex = __shfl_sync(FULL, sc, q);
                float2 f = __half22float2(d_eah[(size_t)k * 32 + lane]);
                te.x = fmaf(ex, f.x, te.x);
                te.y = fmaf(ex, f.y, te.y);
                s += ex;
            }
        }
        tesh[warp][2 * lane]     = te.x;
        tesh[warp][2 * lane + 1] = te.y;
        __syncwarp();
        float v1 = 0.f, v2 = 0.f;
        if (ce > 0) {
            float invz = 1.f / (s * (float)ce);
            const float* tr = tesh[warp];
            #pragma unroll 16
            for (int f = 0; f < FE; f++) {
                float tv = tr[f];
                v1 = fmaf(tv, Wsh[lane * 65 + f], v1);
                v2 = fmaf(tv, Wsh[(lane + 32) * 65 + f], v2);
            }
            v1 *= invz; v2 *= invz;
        }
        out[(size_t)n * 128 + 64 + lane] = leaky(v1);
        out[(size_t)n * 128 + 96 + lane] = leaky(v2);
    }
}

// ---------------- launch ----------------------------------------------------
extern "C" void kernel_launch(void* const* d_in, const int* in_sizes, int n_in,
                              void* d_out, int out_size) {
    const float* x  = (const float*)d_in[0];
    const float* ea = (const float*)d_in[1];
    const void*  ei = d_in[2];
    const float* Wn = (const float*)d_in[3];
    const float* We = (const float*)d_in[4];
    const float* an = (const float*)d_in[5];
    const float* ae = (const float*)d_in[6];
    float* out = (float*)d_out;

    int N = in_sizes[0] / FN;    // 50000
    int E = in_sizes[1] / FE;    // 800000
    int twoE = 2 * E;

    k_init<<<(twoE / 2 + 255) / 256, 256>>>(ei, twoE, N);      // 1
    k_convert_hist<<<(twoE + 255) / 256, 256>>>(ei, twoE, E);  // 2
    k_scan_all<<<1, 1024>>>(N, E);                             // 3
    k_scatter<<<(E + 255) / 256, 256>>>(E);                    // 4 (PROFILED)
    k_u<<<1, 64>>>(We, ae);                                    // 5
    k_ge<<<((long long)E * 16 + 255) / 256, 256>>>(ea, E);     // 6
    k_h<<<(N + 31) / 32, 256>>>(x, Wn, an, ae, N);             // 7
    k_acc<<<(N + 7) / 8, 256>>>(We, out, N);                   // 8
}

// round 17
// speedup vs baseline: 2.1715x; 2.1715x over previous
#include <cuda_runtime.h>
#include <cuda_fp16.h>

// Problem shape (fixed by the dataset): N=50000, E=800000, Fn=128, Fe=64, D=64
#define MAXN 50176
#define MAXE 800000
#define DD   64
#define FN   128
#define FE   64
#define SLOPE 0.05f
#define FULL 0xffffffffu

// ---------------- scratch (device globals; no allocation) ----------------
__device__ __half2 d_h16[MAXN * 32];         // h fp16 [N,64]   (6.4 MB)
__device__ __half2 d_eah[(size_t)MAXE * 32]; // edge_attr fp16  (102 MB)
__device__ float  d_hi[MAXN], d_hj[MAXN], d_he[MAXN];
__device__ float4 d_u4[16];             // u[64] = W_edge^T @ a_edge[D:]
__device__ float  d_ge[MAXE];           // per-edge score part: edge_attr[k].u
__device__ int    d_ei32[2 * MAXE];     // edge indices as int32
__device__ int    d_srcn[MAXE];         // CSR(node): source j per slot
__device__ int    d_srce[2 * MAXE];     // CSR(edge): edge id per slot
__device__ int    d_deg_n[MAXN], d_deg_e[MAXN];
__device__ int    d_off_n[MAXN + 1], d_off_e[MAXN + 1];
__device__ int    d_cur_n[MAXN], d_cur_e[MAXN];
__device__ int    d_part_n[64], d_part_e[64];
__device__ int    d_not64;

__device__ __forceinline__ float leaky(float v) { return v >= 0.f ? v : SLOPE * v; }

// ---------------- K1: zero degree counters + CHEAP dtype detect -------------
// Detection by ONE block over 4096 int64 words (statistically certain:
// if the buffer is int32, a packed pair is in [0,N) only when its high word
// is 0 — probability ~1e-9 per word). No global atomic storm.
__global__ void k_init(const void* __restrict__ ei, int twoE, int N) {
    int i = blockIdx.x * blockDim.x + threadIdx.x;
    if (i < N) { d_deg_n[i] = 0; d_deg_e[i] = 0; }
    if (blockIdx.x == 0) {
        __shared__ int flag;
        if (threadIdx.x == 0) flag = 0;
        __syncthreads();
        int words = twoE / 2;            // int64 words safely readable
        if (words > 4096) words = 4096;
        const long long* p = (const long long*)ei;
        int bad = 0;
        for (int w = threadIdx.x; w < words; w += 256) {
            long long v = p[w];
            if (v < 0 || v >= N) bad = 1;
        }
        if (bad) flag = 1;               // benign race: all writers write 1
        __syncthreads();
        if (threadIdx.x == 0) d_not64 = flag;
    }
}

// ---------------- K2: u[f] = sum_d a_edge[D+d] * W_edge[d][f] ---------------
__global__ void k_u(const float* __restrict__ We, const float* __restrict__ a_edge) {
    int f = threadIdx.x;  // 64 threads
    float acc = 0.f;
    #pragma unroll 8
    for (int dd = 0; dd < DD; dd++) acc = fmaf(a_edge[DD + dd], We[dd * FE + f], acc);
    ((float*)d_u4)[f] = acc;
}

// ---------------- K3: ge[k] = edge_attr[k].u + fp16 staging -----------------
__global__ void k_ge(const float* __restrict__ ea, int E) {
    int tid = blockIdx.x * blockDim.x + threadIdx.x;
    int k = tid >> 4;
    int l = tid & 15;
    bool valid = (k < E);
    int kk = valid ? k : 0;
    const float4* ea4 = (const float4*)ea;
    float4 v = ea4[(size_t)kk * 16 + l];
    if (valid) {
        d_eah[(size_t)k * 32 + 2 * l]     = __floats2half2_rn(v.x, v.y);
        d_eah[(size_t)k * 32 + 2 * l + 1] = __floats2half2_rn(v.z, v.w);
    }
    float4 u = d_u4[l];
    float p = v.x * u.x + v.y * u.y + v.z * u.z + v.w * u.w;
    #pragma unroll
    for (int o = 8; o; o >>= 1) p += __shfl_xor_sync(FULL, p, o, 16);
    if (valid && l == 0) d_ge[k] = p;
}

// ---------------- K4 (PROFILED): convert indices + histogram degrees --------
__global__ void k_convert_hist(const void* __restrict__ ei, int twoE, int E) {
    int i = blockIdx.x * blockDim.x + threadIdx.x;
    if (i >= twoE) return;
    int v;
    if (d_not64) v = ((const int*)ei)[i];
    else         v = (int)((const long long*)ei)[i];
    d_ei32[i] = v;
    if (i < E) atomicAdd(&d_deg_n[v], 1);   // node branch: targets only
    atomicAdd(&d_deg_e[v], 1);              // edge branch: both endpoints
}

// ---------------- K5: h = x @ W_node^T (+ attention dots + fp16 store) ------
__global__ void k_h(const float* __restrict__ x, const float* __restrict__ Wn,
                    const float* __restrict__ an, const float* __restrict__ ae, int N) {
    __shared__ float4 Wsh[64 * 32];   // 32 KB, swizzled
    __shared__ float4 xsh[32 * 32];   // 16 KB
    __shared__ float  hsh[32 * 65];   // 8.3 KB, h tile (padded)
    int t = threadIdx.x;
    const float4* Wn4 = (const float4*)Wn;
    for (int idx = t; idx < 64 * 32; idx += 256) {
        int d = idx >> 5, c4 = idx & 31;
        Wsh[d * 32 + ((c4 + d) & 31)] = Wn4[idx];
    }
    int nb = blockIdx.x * 32;
    const float4* x4 = (const float4*)x;
    for (int idx = t; idx < 32 * 32; idx += 256) {
        int nl = idx >> 5, c4 = idx & 31;
        int n = nb + nl;
        xsh[idx] = (n < N) ? x4[(size_t)n * 32 + c4] : make_float4(0.f, 0.f, 0.f, 0.f);
    }
    __syncthreads();

    int d0 = t & 15, g = t >> 4;
    float acc[2][4] = {};
    #pragma unroll 4
    for (int f4 = 0; f4 < 32; f4++) {
        float4 w[4];
        #pragma unroll
        for (int k = 0; k < 4; k++) {
            int d = d0 + 16 * k;
            w[k] = Wsh[d * 32 + ((f4 + d) & 31)];
        }
        float4 xa = xsh[(g * 2 + 0) * 32 + f4];
        float4 xb = xsh[(g * 2 + 1) * 32 + f4];
        #pragma unroll
        for (int k = 0; k < 4; k++) {
            acc[0][k] = fmaf(xa.x, w[k].x, fmaf(xa.y, w[k].y, fmaf(xa.z, w[k].z, fmaf(xa.w, w[k].w, acc[0][k]))));
            acc[1][k] = fmaf(xb.x, w[k].x, fmaf(xb.y, w[k].y, fmaf(xb.z, w[k].z, fmaf(xb.w, w[k].w, acc[1][k]))));
        }
    }
    #pragma unroll
    for (int s = 0; s < 2; s++) {
        int nl = g * 2 + s;
        #pragma unroll
        for (int k = 0; k < 4; k++)
            hsh[nl * 65 + d0 + 16 * k] = acc[s][k];
    }
    __syncthreads();

    for (int idx = t; idx < 32 * 32; idx += 256) {
        int nl = idx >> 5, c = idx & 31;
        int n = nb + nl;
        if (n < N)
            d_h16[(size_t)n * 32 + c] =
                __floats2half2_rn(hsh[nl * 65 + 2 * c], hsh[nl * 65 + 2 * c + 1]);
    }

    int warp = t >> 5, lane = t & 31;
    for (int q = 0; q < 4; q++) {
        int nl = warp * 4 + q;
        int n = nb + nl;
        float v0 = hsh[nl * 65 + lane];
        float v1 = hsh[nl * 65 + 32 + lane];
        float p1 = v0 * an[lane]      + v1 * an[lane + 32];
        float p2 = v0 * an[64 + lane] + v1 * an[96 + lane];
        float p3 = v0 * ae[lane]      + v1 * ae[lane + 32];
        #pragma unroll
        for (int o = 16; o; o >>= 1) {
            p1 += __shfl_xor_sync(FULL, p1, o);
            p2 += __shfl_xor_sync(FULL, p2, o);
            p3 += __shfl_xor_sync(FULL, p3, o);
        }
        if (lane == 0 && n < N) { d_hi[n] = p1; d_hj[n] = p2; d_he[n] = p3; }
    }
}

// ---------------- scans (3 kernels, chunk=1024 — measured fast in R12) ------
__global__ void k_scanA(int N) {
    __shared__ int sh[1024];
    int t = threadIdx.x, i = blockIdx.x * 1024 + t;
    sh[t] = (i < N) ? d_deg_n[i] : 0;
    __syncthreads();
    for (int o = 512; o; o >>= 1) { if (t < o) sh[t] += sh[t + o]; __syncthreads(); }
    if (t == 0) d_part_n[blockIdx.x] = sh[0];
    __syncthreads();
    sh[t] = (i < N) ? d_deg_e[i] : 0;
    __syncthreads();
    for (int o = 512; o; o >>= 1) { if (t < o) sh[t] += sh[t + o]; __syncthreads(); }
    if (t == 0) d_part_e[blockIdx.x] = sh[0];
}

__global__ void k_scanB(int NB) {
    __shared__ int sn[64], se[64];
    int t = threadIdx.x;
    sn[t] = (t < NB) ? d_part_n[t] : 0;
    se[t] = (t < NB) ? d_part_e[t] : 0;
    __syncthreads();
    for (int o = 1; o < 64; o <<= 1) {
        int a = (t >= o) ? sn[t - o] : 0;
        int b = (t >= o) ? se[t - o] : 0;
        __syncthreads();
        sn[t] += a; se[t] += b;
        __syncthreads();
    }
    if (t < NB) { d_part_n[t] = sn[t]; d_part_e[t] = se[t]; }
}

__global__ void k_scanC(int N) {
    __shared__ int sn[1024], se[1024];
    int b = blockIdx.x, t = threadIdx.x, i = b * 1024 + t;
    int vn = (i < N) ? d_deg_n[i] : 0;
    int ve = (i < N) ? d_deg_e[i] : 0;
    sn[t] = vn; se[t] = ve;
    __syncthreads();
    for (int o = 1; o < 1024; o <<= 1) {
        int a = (t >= o) ? sn[t - o] : 0;
        int c = (t >= o) ? se[t - o] : 0;
        __syncthreads();
        sn[t] += a; se[t] += c;
        __syncthreads();
    }
    int basen = (b > 0) ? d_part_n[b - 1] : 0;
    int basee = (b > 0) ? d_part_e[b - 1] : 0;
    int excln = basen + sn[t] - vn;
    int excle = basee + se[t] - ve;
    if (i < N) {
        d_off_n[i] = excln; d_off_e[i] = excle;
        d_cur_n[i] = excln; d_cur_e[i] = excle;
    }
    if (i == N - 1) { d_off_n[N] = excln + vn; d_off_e[N] = excle + ve; }
}

// ---------------- scatter: permutation only ---------------------------------
__global__ void k_scatter(int E) {
    int k = blockIdx.x * blockDim.x + threadIdx.x;
    if (k >= E) return;
    int i = d_ei32[k], j = d_ei32[E + k];
    int pn = atomicAdd(&d_cur_n[i], 1);
    d_srcn[pn] = j;
    int p1 = atomicAdd(&d_cur_e[i], 1);
    d_srce[p1] = k;
    int p2 = atomicAdd(&d_cur_e[j], 1);
    d_srce[p2] = k;
}

// ---------------- fused accumulate + project + write (warp per node) --------
__global__ void k_acc(const float* __restrict__ We, float* __restrict__ out, int N) {
    __shared__ float Wsh[64 * 65];   // W_edge padded (16.6 KB)
    __shared__ float tesh[8][64];    // per-warp te stage
    int t = threadIdx.x;
    for (int idx = t; idx < 64 * 64; idx += 256)
        Wsh[(idx >> 6) * 65 + (idx & 63)] = We[idx];
    __syncthreads();   // last block-wide sync — safe for early warp returns below

    int warp = t >> 5, lane = t & 31;
    int n = blockIdx.x * 8 + warp;
    if (n >= N) return;

    // ---- node branch ----
    {
        int off = d_off_n[n], end = d_off_n[n + 1];
        float hi_n = d_hi[n];
        float2 acc = make_float2(0.f, 0.f);
        float s = 0.f;   // broadcast loads: every lane holds the full sum
        #pragma unroll 8
        for (int p = off; p < end; p++) {
            int j    = d_srcn[p];
            float ex = __expf(leaky(hi_n + d_hj[j]));
            float2 f = __half22float2(d_h16[(size_t)j * 32 + lane]);
            acc.x = fmaf(ex, f.x, acc.x);
            acc.y = fmaf(ex, f.y, acc.y);
            s += ex;
        }
        float exs = __expf(leaky(hi_n + d_hj[n]));   // self loop
        s += exs;
        float inv = 1.f / (s * (float)(end - off + 1));
        float2 hv = __half22float2(d_h16[(size_t)n * 32 + lane]);
        float2 r;
        r.x = leaky(fmaf(exs, hv.x, acc.x) * inv);
        r.y = leaky(fmaf(exs, hv.y, acc.y) * inv);
        ((float2*)out)[(size_t)n * 64 + lane] = r;   // out[n, 0:64]
    }

    // ---- edge branch ----
    {
        int off = d_off_e[n], end = d_off_e[n + 1];
        int ce = end - off;
        float he_n = d_he[n];
        float2 te = make_float2(0.f, 0.f);
        float s = 0.f;
        #pragma unroll 8
        for (int p = off; p < end; p++) {
            int k    = d_srce[p];
            float ex = __expf(leaky(he_n + d_ge[k]));
            float2 f = __half22float2(d_eah[(size_t)k * 32 + lane]);
            te.x = fmaf(ex, f.x, te.x);
            te.y = fmaf(ex, f.y, te.y);
            s += ex;
        }
        tesh[warp][2 * lane]     = te.x;
        tesh[warp][2 * lane + 1] = te.y;
        __syncwarp();
        float v1 = 0.f, v2 = 0.f;
        if (ce > 0) {
            float invz = 1.f / (s * (float)ce);
            const float* tr = tesh[warp];
            #pragma unroll 16
            for (int f = 0; f < FE; f++) {
                float tv = tr[f];
                v1 = fmaf(tv, Wsh[lane * 65 + f], v1);
                v2 = fmaf(tv, Wsh[(lane + 32) * 65 + f], v2);
            }
            v1 *= invz; v2 *= invz;
        }
        out[(size_t)n * 128 + 64 + lane] = leaky(v1);
        out[(size_t)n * 128 + 96 + lane] = leaky(v2);
    }
}

// ---------------- launch ----------------------------------------------------
extern "C" void kernel_launch(void* const* d_in, const int* in_sizes, int n_in,
                              void* d_out, int out_size) {
    const float* x  = (const float*)d_in[0];
    const float* ea = (const float*)d_in[1];
    const void*  ei = d_in[2];
    const float* Wn = (const float*)d_in[3];
    const float* We = (const float*)d_in[4];
    const float* an = (const float*)d_in[5];
    const float* ae = (const float*)d_in[6];
    float* out = (float*)d_out;

    int N = in_sizes[0] / FN;    // 50000
    int E = in_sizes[1] / FE;    // 800000
    int twoE = 2 * E;
    int NB = (N + 1023) / 1024;  // 49

    k_init<<<(N + 255) / 256, 256>>>(ei, twoE, N);             // 1
    k_u<<<1, 64>>>(We, ae);                                    // 2
    k_ge<<<((long long)E * 16 + 255) / 256, 256>>>(ea, E);     // 3
    k_convert_hist<<<(twoE + 255) / 256, 256>>>(ei, twoE, E);  // 4 (PROFILED)
    k_h<<<(N + 31) / 32, 256>>>(x, Wn, an, ae, N);             // 5
    k_scanA<<<NB, 1024>>>(N);                                  // 6
    k_scanB<<<1, 64>>>(NB);                                    // 7
    k_scanC<<<NB, 1024>>>(N);                                  // 8
    k_scatter<<<(E + 255) / 256, 256>>>(E);                    // 9
    k_acc<<<(N + 7) / 8, 256>>>(We, out, N);                   // 10
}